// round 1
// baseline (speedup 1.0000x reference)
#include <cuda_runtime.h>
#include <stdint.h>

#define NB 32
#define IMG_H 1024
#define IMG_W 1024
#define NPIX (IMG_H * IMG_W)
#define NOFF 16

// Scratch (static device globals — no dynamic allocation)
__device__ unsigned int      g_q32[NB * NPIX / 4];   // quantized image, uint8 packed as u32 (32 MB)
__device__ unsigned int      g_mn[NB];
__device__ unsigned int      g_mx[NB];
__device__ unsigned long long g_sums[NB * NOFF];

// Monotone float <-> uint mapping for atomicMin/Max on floats
__device__ __forceinline__ unsigned int fmap(float f) {
    unsigned int u = __float_as_uint(f);
    return (u & 0x80000000u) ? ~u : (u | 0x80000000u);
}
__device__ __forceinline__ float funmap(unsigned int u) {
    u = (u & 0x80000000u) ? (u & 0x7fffffffu) : ~u;
    return __uint_as_float(u);
}

__global__ void k_init() {
    int t = blockIdx.x * blockDim.x + threadIdx.x;
    if (t < NB) { g_mn[t] = 0xFFFFFFFFu; g_mx[t] = 0u; }
    if (t < NB * NOFF) g_sums[t] = 0ull;
}

__global__ void k_minmax(const float* __restrict__ x) {
    int b = blockIdx.x;
    const float4* xb = (const float4*)(x + (size_t)b * NPIX);
    int idx = blockIdx.y * blockDim.x + threadIdx.x;
    int stride = gridDim.y * blockDim.x;
    float mn = 3.402823466e38f, mx = -3.402823466e38f;
    for (int i = idx; i < NPIX / 4; i += stride) {
        float4 v = xb[i];
        mn = fminf(mn, fminf(fminf(v.x, v.y), fminf(v.z, v.w)));
        mx = fmaxf(mx, fmaxf(fmaxf(v.x, v.y), fmaxf(v.z, v.w)));
    }
#pragma unroll
    for (int o = 16; o; o >>= 1) {
        mn = fminf(mn, __shfl_down_sync(0xffffffffu, mn, o));
        mx = fmaxf(mx, __shfl_down_sync(0xffffffffu, mx, o));
    }
    if ((threadIdx.x & 31) == 0) {
        atomicMin(&g_mn[b], fmap(mn));
        atomicMax(&g_mx[b], fmap(mx));
    }
}

__global__ void k_quant(const float* __restrict__ x) {
    int i = blockIdx.x * blockDim.x + threadIdx.x;  // u32 index (4 pixels)
    if (i >= NB * NPIX / 4) return;
    int b = i >> 18;  // NPIX/4 = 2^18 u32 per image
    float mn = funmap(g_mn[b]);
    float mx = funmap(g_mx[b]);
    float rng = mx - mn;
    float4 v = ((const float4*)x)[i];
    int q0 = (int)((255.0f * (v.x - mn)) / rng);
    int q1 = (int)((255.0f * (v.y - mn)) / rng);
    int q2 = (int)((255.0f * (v.z - mn)) / rng);
    int q3 = (int)((255.0f * (v.w - mn)) / rng);
    q0 = min(max(q0, 0), 255); q1 = min(max(q1, 0), 255);
    q2 = min(max(q2, 0), 255); q3 = min(max(q3, 0), 255);
    g_q32[i] = (unsigned)q0 | ((unsigned)q1 << 8) | ((unsigned)q2 << 16) | ((unsigned)q3 << 24);
}

// Offset tables (order: for d in {1,3,5,7}, for angle in {0,45,90,135}: (dr, dc))
#define DR_TAB {0,1,1,1, 0,2,3,2, 0,4,5,4, 0,5,7,5}
#define DC_TAB {1,1,0,-1, 3,2,0,-2, 5,4,0,-4, 7,5,0,-5}

// Extract the 4 bytes starting at byte offset (sb) within the 8-u32 window Warr
// (window byte 0 corresponds to image column c-8; sb is a compile-time constant)
#define EXT(sb) ( ((sb) & 3) ? __funnelshift_r(Warr[(sb) >> 2], Warr[((sb) >> 2) + 1], ((sb) & 3) * 8) \
                             : Warr[(sb) >> 2] )
#define ACC1(o, gg, dc) { unsigned int _n = EXT(8 + 4*(gg) + (dc)); \
                          unsigned int _d = __vabsdiffu4(S[gg], _n); \
                          acc[o] = __dp4a(_d, _d, acc[o]); }
#define ACC4(o, dc) { ACC1(o, 0, dc) ACC1(o, 1, dc) ACC1(o, 2, dc) ACC1(o, 3, dc) }
#define LOADW(rp) { Warr[0]=(rp)[-2]; Warr[1]=(rp)[-1]; Warr[2]=(rp)[0]; Warr[3]=(rp)[1]; \
                    Warr[4]=(rp)[2];  Warr[5]=(rp)[3];  Warr[6]=(rp)[4]; Warr[7]=(rp)[5]; }

__global__ void __launch_bounds__(256) k_ssd() {
    int b = blockIdx.y;
    int tid = threadIdx.x;
    int r = blockIdx.x * 4 + (tid >> 6);   // source row
    int g = tid & 63;                      // 16-pixel group in row
    int c = g << 4;                        // starting column
    const unsigned int* qb = g_q32 + (size_t)b * (NPIX / 4);

    unsigned int acc[NOFF];
#pragma unroll
    for (int o = 0; o < NOFF; o++) acc[o] = 0;

    if (g >= 1 && g <= 62 && r <= IMG_H - 8) {
        // Fast interior path: all 16 offsets fully in-bounds for all 16 pixels.
        const unsigned int* p = qb + r * (IMG_W / 4) + (c >> 2);
        unsigned int S[4] = { p[0], p[1], p[2], p[3] };
        unsigned int Warr[8];

        LOADW(p);                     // dr = 0
        ACC4(0, 1)  ACC4(4, 3)  ACC4(8, 5)  ACC4(12, 7)
        LOADW(p + 256);               // dr = 1
        ACC4(1, 1)  ACC4(2, 0)  ACC4(3, -1)
        LOADW(p + 512);               // dr = 2
        ACC4(5, 2)  ACC4(7, -2)
        LOADW(p + 768);               // dr = 3
        ACC4(6, 0)
        LOADW(p + 1024);              // dr = 4
        ACC4(9, 4)  ACC4(11, -4)
        LOADW(p + 1280);              // dr = 5
        ACC4(10, 0) ACC4(13, 5) ACC4(15, -5)
        LOADW(p + 1792);              // dr = 7
        ACC4(14, 0)
    } else {
        // Boundary path: per-pixel, per-offset bounds checks.
        const uint8_t* qB = (const uint8_t*)qb;
        const int DR[NOFF] = DR_TAB;
        const int DC[NOFF] = DC_TAB;
        for (int i = 0; i < 16; i++) {
            int cc = c + i;
            int a = qB[r * IMG_W + cc];
#pragma unroll
            for (int o = 0; o < NOFF; o++) {
                int rr = r + DR[o];
                int c2 = cc + DC[o];
                if (rr < IMG_H && c2 >= 0 && c2 < IMG_W) {
                    int d = a - (int)qB[rr * IMG_W + c2];
                    acc[o] += (unsigned)(d * d);
                }
            }
        }
    }

    // Warp reduce each of the 16 accumulators
#pragma unroll
    for (int o = 0; o < NOFF; o++) {
#pragma unroll
        for (int s = 16; s; s >>= 1)
            acc[o] += __shfl_down_sync(0xffffffffu, acc[o], s);
    }

    __shared__ unsigned int part[8][NOFF];
    int warp = tid >> 5, lane = tid & 31;
    if (lane == 0) {
#pragma unroll
        for (int o = 0; o < NOFF; o++) part[warp][o] = acc[o];
    }
    __syncthreads();
    if (tid < NOFF) {
        unsigned long long s = 0;
#pragma unroll
        for (int w = 0; w < 8; w++) s += part[w][tid];
        atomicAdd(&g_sums[b * NOFF + tid], s);
    }
}

__global__ void k_final(float* __restrict__ out) {
    int t = blockIdx.x * blockDim.x + threadIdx.x;
    if (t >= NB * NOFF) return;
    const int DR[NOFF] = DR_TAB;
    const int DC[NOFF] = DC_TAB;
    int o = t & 15;
    int adc = DC[o] < 0 ? -DC[o] : DC[o];
    double cnt = (double)(IMG_H - DR[o]) * (double)(IMG_W - adc);
    out[t] = (float)((double)g_sums[t] / cnt);
}

extern "C" void kernel_launch(void* const* d_in, const int* in_sizes, int n_in,
                              void* d_out, int out_size) {
    const float* x = (const float*)d_in[0];
    float* out = (float*)d_out;

    k_init<<<1, 512>>>();
    k_minmax<<<dim3(NB, 16), 256>>>(x);
    k_quant<<<(NB * NPIX / 4 + 255) / 256, 256>>>(x);
    k_ssd<<<dim3(IMG_H / 4, NB), 256>>>();
    k_final<<<2, 256>>>(out);
}

// round 6
// speedup vs baseline: 1.0823x; 1.0823x over previous
#include <cuda_runtime.h>
#include <stdint.h>

#define NB 32
#define IMG_H 1024
#define IMG_W 1024
#define NPIX (IMG_H * IMG_W)
#define NOFF 16

// Scratch (static device globals — no dynamic allocation)
__device__ unsigned int       g_q32[NB * NPIX / 4];   // quantized image, uint8 packed (32 MB)
__device__ unsigned int       g_mn[NB];
__device__ unsigned int       g_mx[NB];
__device__ unsigned long long g_sums[NB * NOFF];

// Monotone float <-> uint mapping for atomicMin/Max on floats
__device__ __forceinline__ unsigned int fmap(float f) {
    unsigned int u = __float_as_uint(f);
    return (u & 0x80000000u) ? ~u : (u | 0x80000000u);
}
__device__ __forceinline__ float funmap(unsigned int u) {
    u = (u & 0x80000000u) ? (u & 0x7fffffffu) : ~u;
    return __uint_as_float(u);
}

__global__ void k_init() {
    int t = blockIdx.x * blockDim.x + threadIdx.x;
    if (t < NB) { g_mn[t] = 0xFFFFFFFFu; g_mx[t] = 0u; }
    if (t < NB * NOFF) g_sums[t] = 0ull;
}

__global__ void k_minmax(const float* __restrict__ x) {
    int b = blockIdx.x;
    const float4* xb = (const float4*)(x + (size_t)b * NPIX);
    int idx = blockIdx.y * blockDim.x + threadIdx.x;
    int stride = gridDim.y * blockDim.x;
    float mn = 3.402823466e38f, mx = -3.402823466e38f;
    for (int i = idx; i < NPIX / 4; i += stride) {
        float4 v = xb[i];
        mn = fminf(mn, fminf(fminf(v.x, v.y), fminf(v.z, v.w)));
        mx = fmaxf(mx, fmaxf(fmaxf(v.x, v.y), fmaxf(v.z, v.w)));
    }
#pragma unroll
    for (int o = 16; o; o >>= 1) {
        mn = fminf(mn, __shfl_down_sync(0xffffffffu, mn, o));
        mx = fmaxf(mx, __shfl_down_sync(0xffffffffu, mx, o));
    }
    if ((threadIdx.x & 31) == 0) {
        atomicMin(&g_mn[b], fmap(mn));
        atomicMax(&g_mx[b], fmap(mx));
    }
}

__global__ void k_quant(const float* __restrict__ x) {
    int i = blockIdx.x * blockDim.x + threadIdx.x;  // u32 index (4 pixels)
    if (i >= NB * NPIX / 4) return;
    int b = i >> 18;  // NPIX/4 = 2^18 u32 per image
    float mn = funmap(g_mn[b]);
    float mx = funmap(g_mx[b]);
    float rng = mx - mn;
    float4 v = ((const float4*)x)[i];
    int q0 = (int)((255.0f * (v.x - mn)) / rng);
    int q1 = (int)((255.0f * (v.y - mn)) / rng);
    int q2 = (int)((255.0f * (v.z - mn)) / rng);
    int q3 = (int)((255.0f * (v.w - mn)) / rng);
    q0 = min(max(q0, 0), 255); q1 = min(max(q1, 0), 255);
    q2 = min(max(q2, 0), 255); q3 = min(max(q3, 0), 255);
    g_q32[i] = (unsigned)q0 | ((unsigned)q1 << 8) | ((unsigned)q2 << 16) | ((unsigned)q3 << 24);
}

// Offset tables (order: for d in {1,3,5,7}, for angle in {0,45,90,135}: (dr, dc))
#define DR_TAB {0,1,1,1, 0,2,3,2, 0,4,5,4, 0,5,7,5}
#define DC_TAB {1,1,0,-1, 3,2,0,-2, 5,4,0,-4, 7,5,0,-5}

// Window W.u[12] covers image bytes [c-16, c+32). Column (c + j) -> window byte (16 + j).
// EXTW(sb): 4 bytes starting at window byte sb (compile-time constant).
#define EXTW(sb) ( ((sb) & 3) ? __funnelshift_r(W.u[(sb) >> 2], W.u[((sb) >> 2) + 1], ((sb) & 3) * 8) \
                              : W.u[(sb) >> 2] )
#define ACC1(o, gg, dc) { unsigned int _n = EXTW(16 + 4*(gg) + (dc)); \
                          unsigned int _d = __vabsdiffu4(S[gg], _n); \
                          acc[o] = __dp4a(_d, _d, acc[o]); }
#define ACC4(o, dc) { ACC1(o, 0, dc) ACC1(o, 1, dc) ACC1(o, 2, dc) ACC1(o, 3, dc) }

__global__ void __launch_bounds__(256) k_ssd() {
    int b = blockIdx.y;
    int tid = threadIdx.x;
    int r = blockIdx.x * 4 + (tid >> 6);   // source row
    int g = tid & 63;                      // 16-pixel group in row
    int c = g << 4;                        // starting column
    const unsigned int* qb = g_q32 + (size_t)b * (NPIX / 4);

    unsigned int acc[NOFF];
#pragma unroll
    for (int o = 0; o < NOFF; o++) acc[o] = 0;

    if (g >= 1 && g <= 62 && r <= IMG_H - 8) {
        // Fast interior path: all 16 offsets fully in-bounds for all 16 pixels.
        // P4 points at column c of row r; one image row = 64 uint4.
        const uint4* P4 = (const uint4*)(qb + r * (IMG_W / 4)) + g;
        union { uint4 v[3]; unsigned int u[12]; } W;
        unsigned int S[4];

        // dr = 0 : dc = 1,3,5,7  (window bytes 17..38 -> v1,v2)
        W.v[1] = P4[0];  W.v[2] = P4[1];
        S[0] = W.u[4]; S[1] = W.u[5]; S[2] = W.u[6]; S[3] = W.u[7];
        ACC4(0, 1)  ACC4(4, 3)  ACC4(8, 5)  ACC4(12, 7)

        { // dr = 1 : dc = -1,0,1  (bytes 15..32 -> v0,v1,v2)
            const uint4* rp = P4 + 64;
            W.v[0] = rp[-1]; W.v[1] = rp[0]; W.v[2] = rp[1];
            ACC4(1, 1)  ACC4(2, 0)  ACC4(3, -1)
        }
        { // dr = 2 : dc = -2,2   (bytes 14..33)
            const uint4* rp = P4 + 128;
            W.v[0] = rp[-1]; W.v[1] = rp[0]; W.v[2] = rp[1];
            ACC4(5, 2)  ACC4(7, -2)
        }
        { // dr = 3 : dc = 0      (bytes 16..31 -> v1 only)
            const uint4* rp = P4 + 192;
            W.v[1] = rp[0];
            ACC4(6, 0)
        }
        { // dr = 4 : dc = -4,4   (bytes 12..35)
            const uint4* rp = P4 + 256;
            W.v[0] = rp[-1]; W.v[1] = rp[0]; W.v[2] = rp[1];
            ACC4(9, 4)  ACC4(11, -4)
        }
        { // dr = 5 : dc = -5,0,5 (bytes 11..36)
            const uint4* rp = P4 + 320;
            W.v[0] = rp[-1]; W.v[1] = rp[0]; W.v[2] = rp[1];
            ACC4(10, 0) ACC4(13, 5) ACC4(15, -5)
        }
        { // dr = 7 : dc = 0      (bytes 16..31 -> v1 only)
            const uint4* rp = P4 + 448;
            W.v[1] = rp[0];
            ACC4(14, 0)
        }
    } else {
        // Boundary path: per-pixel, per-offset bounds checks.
        const uint8_t* qB = (const uint8_t*)qb;
        const int DR[NOFF] = DR_TAB;
        const int DC[NOFF] = DC_TAB;
        for (int i = 0; i < 16; i++) {
            int cc = c + i;
            int a = qB[r * IMG_W + cc];
#pragma unroll
            for (int o = 0; o < NOFF; o++) {
                int rr = r + DR[o];
                int c2 = cc + DC[o];
                if (rr < IMG_H && c2 >= 0 && c2 < IMG_W) {
                    int d = a - (int)qB[rr * IMG_W + c2];
                    acc[o] += (unsigned)(d * d);
                }
            }
        }
    }

    // Single-instruction warp reduction per accumulator (REDUX.SUM)
#pragma unroll
    for (int o = 0; o < NOFF; o++)
        acc[o] = __reduce_add_sync(0xffffffffu, acc[o]);

    __shared__ unsigned int part[8][NOFF];
    int warp = tid >> 5, lane = tid & 31;
    if (lane == 0) {
#pragma unroll
        for (int o = 0; o < NOFF; o++) part[warp][o] = acc[o];
    }
    __syncthreads();
    if (tid < NOFF) {
        unsigned long long s = 0;
#pragma unroll
        for (int w = 0; w < 8; w++) s += part[w][tid];
        atomicAdd(&g_sums[b * NOFF + tid], s);
    }
}

__global__ void k_final(float* __restrict__ out) {
    int t = blockIdx.x * blockDim.x + threadIdx.x;
    if (t >= NB * NOFF) return;
    const int DR[NOFF] = DR_TAB;
    const int DC[NOFF] = DC_TAB;
    int o = t & 15;
    int adc = DC[o] < 0 ? -DC[o] : DC[o];
    double cnt = (double)(IMG_H - DR[o]) * (double)(IMG_W - adc);
    out[t] = (float)((double)g_sums[t] / cnt);
}

extern "C" void kernel_launch(void* const* d_in, const int* in_sizes, int n_in,
                              void* d_out, int out_size) {
    const float* x = (const float*)d_in[0];
    float* out = (float*)d_out;

    k_init<<<1, 512>>>();
    k_minmax<<<dim3(NB, 16), 256>>>(x);
    k_quant<<<(NB * NPIX / 4 + 255) / 256, 256>>>(x);
    k_ssd<<<dim3(IMG_H / 4, NB), 256>>>();
    k_final<<<2, 256>>>(out);
}

// round 7
// speedup vs baseline: 1.9868x; 1.8358x over previous
#include <cuda_runtime.h>
#include <stdint.h>

#define NB 32
#define IMG_H 1024
#define IMG_W 1024
#define NPIX (IMG_H * IMG_W)
#define NOFF 16

// Scratch (static device globals — no dynamic allocation)
__device__ unsigned int       g_q32[NB * NPIX / 4];   // quantized image, uint8 packed (32 MB)
__device__ unsigned int       g_mn[NB];
__device__ unsigned int       g_mx[NB];
__device__ unsigned long long g_sums[NB * NOFF];

// Monotone float <-> uint mapping for atomicMin/Max on floats
__device__ __forceinline__ unsigned int fmap(float f) {
    unsigned int u = __float_as_uint(f);
    return (u & 0x80000000u) ? ~u : (u | 0x80000000u);
}
__device__ __forceinline__ float funmap(unsigned int u) {
    u = (u & 0x80000000u) ? (u & 0x7fffffffu) : ~u;
    return __uint_as_float(u);
}

__global__ void k_init() {
    int t = blockIdx.x * blockDim.x + threadIdx.x;
    if (t < NB) { g_mn[t] = 0xFFFFFFFFu; g_mx[t] = 0u; }
    if (t < NB * NOFF) g_sums[t] = 0ull;
}

__global__ void k_minmax(const float* __restrict__ x) {
    int b = blockIdx.x;
    const float4* xb = (const float4*)(x + (size_t)b * NPIX);
    int idx = blockIdx.y * blockDim.x + threadIdx.x;
    int stride = gridDim.y * blockDim.x;
    float mn = 3.402823466e38f, mx = -3.402823466e38f;
    for (int i = idx; i < NPIX / 4; i += stride) {
        float4 v = xb[i];
        mn = fminf(mn, fminf(fminf(v.x, v.y), fminf(v.z, v.w)));
        mx = fmaxf(mx, fmaxf(fmaxf(v.x, v.y), fmaxf(v.z, v.w)));
    }
#pragma unroll
    for (int o = 16; o; o >>= 1) {
        mn = fminf(mn, __shfl_down_sync(0xffffffffu, mn, o));
        mx = fmaxf(mx, __shfl_down_sync(0xffffffffu, mx, o));
    }
    if ((threadIdx.x & 31) == 0) {
        atomicMin(&g_mn[b], fmap(mn));
        atomicMax(&g_mx[b], fmap(mx));
    }
}

__global__ void k_quant(const float* __restrict__ x) {
    int i = blockIdx.x * blockDim.x + threadIdx.x;  // u32 index (4 pixels)
    if (i >= NB * NPIX / 4) return;
    int b = i >> 18;  // NPIX/4 = 2^18 u32 per image
    float mn = funmap(g_mn[b]);
    float mx = funmap(g_mx[b]);
    float rng = mx - mn;
    float4 v = ((const float4*)x)[i];
    int q0 = (int)((255.0f * (v.x - mn)) / rng);
    int q1 = (int)((255.0f * (v.y - mn)) / rng);
    int q2 = (int)((255.0f * (v.z - mn)) / rng);
    int q3 = (int)((255.0f * (v.w - mn)) / rng);
    q0 = min(max(q0, 0), 255); q1 = min(max(q1, 0), 255);
    q2 = min(max(q2, 0), 255); q3 = min(max(q3, 0), 255);
    g_q32[i] = (unsigned)q0 | ((unsigned)q1 << 8) | ((unsigned)q2 << 16) | ((unsigned)q3 << 24);
}

// Offset tables (order: for d in {1,3,5,7}, for angle in {0,45,90,135}: (dr, dc))
#define DR_TAB {0,1,1,1, 0,2,3,2, 0,4,5,4, 0,5,7,5}
#define DC_TAB {1,1,0,-1, 3,2,0,-2, 5,4,0,-4, 7,5,0,-5}

// Window W.u[12] covers image bytes [c-16, c+32). Column (c + j) -> window byte (16 + j).
// EXTW(sb): 4 bytes starting at window byte sb (compile-time constant).
#define EXTW(sb) ( ((sb) & 3) ? __funnelshift_r(W.u[(sb) >> 2], W.u[((sb) >> 2) + 1], ((sb) & 3) * 8) \
                              : W.u[(sb) >> 2] )
#define ACC1(o, gg, dc) { unsigned int _n = EXTW(16 + 4*(gg) + (dc)); \
                          unsigned int _d = __vabsdiffu4(S[gg], _n); \
                          acc[o] = __dp4a(_d, _d, acc[o]); }
#define ACC4(o, dc) { ACC1(o, 0, dc) ACC1(o, 1, dc) ACC1(o, 2, dc) ACC1(o, 3, dc) }

// Interior-only kernel: r in [0, 1016), columns [16, 1008). Branch-free hot loop.
__global__ void __launch_bounds__(256) k_ssd() {
    int b = blockIdx.y;
    int tid = threadIdx.x;
    int r = blockIdx.x * 4 + (tid >> 6);   // source row, 0..1015
    int lg = tid & 63;                     // 0..63 -> group g = lg+1 (1..62 valid)
    int g = lg + 1;
    const unsigned int* qb = g_q32 + (size_t)b * (NPIX / 4);

    unsigned int acc[NOFF];
#pragma unroll
    for (int o = 0; o < NOFF; o++) acc[o] = 0;

    if (lg < 62) {
        // All 16 offsets fully in-bounds for all 16 pixels of this group.
        const uint4* P4 = (const uint4*)(qb + r * (IMG_W / 4)) + g;
        union { uint4 v[3]; unsigned int u[12]; } W;
        unsigned int S[4];

        // dr = 0 : dc = 1,3,5,7  (window bytes 17..38 -> v1,v2)
        W.v[1] = P4[0];  W.v[2] = P4[1];
        S[0] = W.u[4]; S[1] = W.u[5]; S[2] = W.u[6]; S[3] = W.u[7];
        ACC4(0, 1)  ACC4(4, 3)  ACC4(8, 5)  ACC4(12, 7)

        { // dr = 1 : dc = -1,0,1
            const uint4* rp = P4 + 64;
            W.v[0] = rp[-1]; W.v[1] = rp[0]; W.v[2] = rp[1];
            ACC4(1, 1)  ACC4(2, 0)  ACC4(3, -1)
        }
        { // dr = 2 : dc = -2,2
            const uint4* rp = P4 + 128;
            W.v[0] = rp[-1]; W.v[1] = rp[0]; W.v[2] = rp[1];
            ACC4(5, 2)  ACC4(7, -2)
        }
        { // dr = 3 : dc = 0
            const uint4* rp = P4 + 192;
            W.v[1] = rp[0];
            ACC4(6, 0)
        }
        { // dr = 4 : dc = -4,4
            const uint4* rp = P4 + 256;
            W.v[0] = rp[-1]; W.v[1] = rp[0]; W.v[2] = rp[1];
            ACC4(9, 4)  ACC4(11, -4)
        }
        { // dr = 5 : dc = -5,0,5
            const uint4* rp = P4 + 320;
            W.v[0] = rp[-1]; W.v[1] = rp[0]; W.v[2] = rp[1];
            ACC4(10, 0) ACC4(13, 5) ACC4(15, -5)
        }
        { // dr = 7 : dc = 0
            const uint4* rp = P4 + 448;
            W.v[1] = rp[0];
            ACC4(14, 0)
        }
    }

    // Single-instruction warp reduction per accumulator (REDUX.SUM)
#pragma unroll
    for (int o = 0; o < NOFF; o++)
        acc[o] = __reduce_add_sync(0xffffffffu, acc[o]);

    __shared__ unsigned int part[8][NOFF];
    int warp = tid >> 5, lane = tid & 31;
    if (lane == 0) {
#pragma unroll
        for (int o = 0; o < NOFF; o++) part[warp][o] = acc[o];
    }
    __syncthreads();
    if (tid < NOFF) {
        unsigned long long s = 0;
#pragma unroll
        for (int w = 0; w < 8; w++) s += part[w][tid];
        atomicAdd(&g_sums[b * NOFF + tid], s);
    }
}

// Border kernel: side columns (c<16 or c>=1008) for r in [0,1016), plus rows 1016..1023
// full width. 40704 pixels per image; per-pixel, per-offset bounds checks.
#define N_SIDE (1016 * 32)          // 32512
#define N_BORD (N_SIDE + 8 * 1024)  // 40704

__global__ void __launch_bounds__(256) k_border() {
    int b = blockIdx.y;
    int tid = threadIdx.x;
    int idx = blockIdx.x * 256 + tid;

    unsigned int acc[NOFF];
#pragma unroll
    for (int o = 0; o < NOFF; o++) acc[o] = 0;

    if (idx < N_BORD) {
        int r, c;
        if (idx < N_SIDE) {
            r = idx >> 5;
            int cc = idx & 31;
            c = (cc < 16) ? cc : cc + 992;   // 0..15 or 1008..1023
        } else {
            int i2 = idx - N_SIDE;
            r = 1016 + (i2 >> 10);
            c = i2 & 1023;
        }
        const uint8_t* qB = (const uint8_t*)(g_q32 + (size_t)b * (NPIX / 4));
        int a = qB[r * IMG_W + c];
        const int DR[NOFF] = DR_TAB;
        const int DC[NOFF] = DC_TAB;
#pragma unroll
        for (int o = 0; o < NOFF; o++) {
            int rr = r + DR[o];
            int c2 = c + DC[o];
            if (rr < IMG_H && c2 >= 0 && c2 < IMG_W) {
                int d = a - (int)qB[rr * IMG_W + c2];
                acc[o] += (unsigned)(d * d);
            }
        }
    }

#pragma unroll
    for (int o = 0; o < NOFF; o++)
        acc[o] = __reduce_add_sync(0xffffffffu, acc[o]);

    __shared__ unsigned int part[8][NOFF];
    int warp = tid >> 5, lane = tid & 31;
    if (lane == 0) {
#pragma unroll
        for (int o = 0; o < NOFF; o++) part[warp][o] = acc[o];
    }
    __syncthreads();
    if (tid < NOFF) {
        unsigned long long s = 0;
#pragma unroll
        for (int w = 0; w < 8; w++) s += part[w][tid];
        atomicAdd(&g_sums[b * NOFF + tid], s);
    }
}

__global__ void k_final(float* __restrict__ out) {
    int t = blockIdx.x * blockDim.x + threadIdx.x;
    if (t >= NB * NOFF) return;
    const int DR[NOFF] = DR_TAB;
    const int DC[NOFF] = DC_TAB;
    int o = t & 15;
    int adc = DC[o] < 0 ? -DC[o] : DC[o];
    double cnt = (double)(IMG_H - DR[o]) * (double)(IMG_W - adc);
    out[t] = (float)((double)g_sums[t] / cnt);
}

extern "C" void kernel_launch(void* const* d_in, const int* in_sizes, int n_in,
                              void* d_out, int out_size) {
    const float* x = (const float*)d_in[0];
    float* out = (float*)d_out;

    k_init<<<1, 512>>>();
    k_minmax<<<dim3(NB, 16), 256>>>(x);
    k_quant<<<(NB * NPIX / 4 + 255) / 256, 256>>>(x);
    k_ssd<<<dim3(254, NB), 256>>>();       // interior: rows 0..1015, cols 16..1007
    k_border<<<dim3((N_BORD + 255) / 256, NB), 256>>>();
    k_final<<<2, 256>>>(out);
}

// round 8
// speedup vs baseline: 3.1587x; 1.5898x over previous
#include <cuda_runtime.h>
#include <stdint.h>

#define NB 32
#define IMG_H 1024
#define IMG_W 1024
#define NPIX (IMG_H * IMG_W)
#define NOFF 16
#define NPART 16           // min/max partial blocks per image
#define TILE_R 32          // rows per fused block
#define SROWS (TILE_R + 7) // + halo rows for dr up to 7

// Scratch (static device globals — no dynamic allocation)
__device__ float               g_pmn[NB * NPART];
__device__ float               g_pmx[NB * NPART];
__device__ unsigned long long  g_sums[NB * NOFF];

// Offset tables (order: for d in {1,3,5,7}, angle {0,45,90,135}: (dr, dc))
#define DR_TAB {0,1,1,1, 0,2,3,2, 0,4,5,4, 0,5,7,5}
#define DC_TAB {1,1,0,-1, 3,2,0,-2, 5,4,0,-4, 7,5,0,-5}

// ---------------------------------------------------------------------------
// Pass 1: per-image min/max partials (one partial per block, no atomics) and
// zero g_sums (block y==0).
// ---------------------------------------------------------------------------
__global__ void __launch_bounds__(256) k_minmax(const float* __restrict__ x) {
    int b = blockIdx.x, y = blockIdx.y;
    int tid = threadIdx.x;
    const float4* xb = (const float4*)(x + (size_t)b * NPIX);

    if (y == 0 && tid < NOFF) g_sums[b * NOFF + tid] = 0ull;

    float mn = 3.402823466e38f, mx = -3.402823466e38f;
    int idx = y * 256 + tid;
    int stride = NPART * 256;
#pragma unroll 4
    for (int i = idx; i < NPIX / 4; i += stride) {
        float4 v = xb[i];
        mn = fminf(mn, fminf(fminf(v.x, v.y), fminf(v.z, v.w)));
        mx = fmaxf(mx, fmaxf(fmaxf(v.x, v.y), fmaxf(v.z, v.w)));
    }
#pragma unroll
    for (int o = 16; o; o >>= 1) {
        mn = fminf(mn, __shfl_down_sync(0xffffffffu, mn, o));
        mx = fmaxf(mx, __shfl_down_sync(0xffffffffu, mx, o));
    }
    __shared__ float smn[8], smx[8];
    int warp = tid >> 5;
    if ((tid & 31) == 0) { smn[warp] = mn; smx[warp] = mx; }
    __syncthreads();
    if (tid == 0) {
        float a = smn[0], c = smx[0];
#pragma unroll
        for (int w = 1; w < 8; w++) { a = fminf(a, smn[w]); c = fmaxf(c, smx[w]); }
        g_pmn[b * NPART + y] = a;
        g_pmx[b * NPART + y] = c;
    }
}

// ---------------------------------------------------------------------------
// Pass 2: fused quantize (to smem) + SSD (interior fast path + tile borders).
// Window W.u[12] covers tile bytes [c-16, c+32). Column (c+j) -> byte (16+j).
// ---------------------------------------------------------------------------
#define EXTW(sb) ( ((sb) & 3) ? __funnelshift_r(W.u[(sb) >> 2], W.u[((sb) >> 2) + 1], ((sb) & 3) * 8) \
                              : W.u[(sb) >> 2] )
#define ACC1(o, gg, dc) { unsigned int _n = EXTW(16 + 4*(gg) + (dc)); \
                          unsigned int _d = __vabsdiffu4(S[gg], _n); \
                          acc[o] = __dp4a(_d, _d, acc[o]); }
#define ACC4(o, dc) { ACC1(o, 0, dc) ACC1(o, 1, dc) ACC1(o, 2, dc) ACC1(o, 3, dc) }

__global__ void __launch_bounds__(256) k_fused(const float* __restrict__ x) {
    __shared__ __align__(16) unsigned int sq[SROWS * 256];  // 39 KB quantized tile
    __shared__ unsigned int part[8][NOFF];

    int b  = blockIdx.y;
    int r0 = blockIdx.x << 5;      // first source row of this tile
    int tid = threadIdx.x;

    // Reduce the 16 min/max partials (uniform across block; broadcast loads)
    float mn = g_pmn[b * NPART], mx = g_pmx[b * NPART];
#pragma unroll
    for (int i = 1; i < NPART; i++) {
        mn = fminf(mn, g_pmn[b * NPART + i]);
        mx = fmaxf(mx, g_pmx[b * NPART + i]);
    }
    float scale = 255.0f / (mx - mn);
    float bias  = -mn * scale;

    // --- Quantize tile rows r0 .. r0+38 into smem (row k -> sq[k*256 ..]) ---
    const float4* xb = (const float4*)x + ((size_t)b << 18);  // 2^18 float4 / image
#pragma unroll
    for (int k = 0; k < SROWS; k++) {
        int gr = r0 + k;
        unsigned int w = 0;
        if (gr < IMG_H) {
            float4 v = xb[gr * 256 + tid];
            int q0 = min((int)fmaf(v.x, scale, bias), 255);
            int q1 = min((int)fmaf(v.y, scale, bias), 255);
            int q2 = min((int)fmaf(v.z, scale, bias), 255);
            int q3 = min((int)fmaf(v.w, scale, bias), 255);
            w = (unsigned)q0 | ((unsigned)q1 << 8) | ((unsigned)q2 << 16) | ((unsigned)q3 << 24);
        }
        sq[k * 256 + tid] = w;
    }
    __syncthreads();

    unsigned int acc[NOFF];
#pragma unroll
    for (int o = 0; o < NOFF; o++) acc[o] = 0;

    // --- Interior fast path: 32 rows x 62 groups, 8 slots per thread ---
    for (int k = 0; k < 8; k++) {
        int slot = tid + (k << 8);
        int ri = slot >> 6;            // row in tile 0..31
        int lg = slot & 63;            // group-1: valid 0..61 -> g=1..62
        if (lg < 62 && (r0 + ri) < 1016) {
            const uint4* P4 = (const uint4*)(sq + ri * 256) + (lg + 1);
            union { uint4 v[3]; unsigned int u[12]; } W;
            unsigned int S[4];

            // dr = 0 : dc = 1,3,5,7
            W.v[1] = P4[0];  W.v[2] = P4[1];
            S[0] = W.u[4]; S[1] = W.u[5]; S[2] = W.u[6]; S[3] = W.u[7];
            ACC4(0, 1)  ACC4(4, 3)  ACC4(8, 5)  ACC4(12, 7)
            { // dr = 1 : dc = -1,0,1
                const uint4* rp = P4 + 64;
                W.v[0] = rp[-1]; W.v[1] = rp[0]; W.v[2] = rp[1];
                ACC4(1, 1)  ACC4(2, 0)  ACC4(3, -1)
            }
            { // dr = 2 : dc = -2,2
                const uint4* rp = P4 + 128;
                W.v[0] = rp[-1]; W.v[1] = rp[0]; W.v[2] = rp[1];
                ACC4(5, 2)  ACC4(7, -2)
            }
            { // dr = 3 : dc = 0
                const uint4* rp = P4 + 192;
                W.v[1] = rp[0];
                ACC4(6, 0)
            }
            { // dr = 4 : dc = -4,4
                const uint4* rp = P4 + 256;
                W.v[0] = rp[-1]; W.v[1] = rp[0]; W.v[2] = rp[1];
                ACC4(9, 4)  ACC4(11, -4)
            }
            { // dr = 5 : dc = -5,0,5
                const uint4* rp = P4 + 320;
                W.v[0] = rp[-1]; W.v[1] = rp[0]; W.v[2] = rp[1];
                ACC4(10, 0) ACC4(13, 5) ACC4(15, -5)
            }
            { // dr = 7 : dc = 0
                const uint4* rp = P4 + 448;
                W.v[1] = rp[0];
                ACC4(14, 0)
            }
        }
    }

    // --- Side-column borders of this tile (c<16 or c>=1008), rows < 1016 ---
    {
        const uint8_t* sb = (const uint8_t*)sq;
        const int DR[NOFF] = DR_TAB;
        const int DC[NOFF] = DC_TAB;
#pragma unroll 1
        for (int idx = tid; idx < TILE_R * 32; idx += 256) {
            int r_in = idx >> 5;
            int cc = idx & 31;
            int c = (cc < 16) ? cc : cc + 992;
            if ((r0 + r_in) < 1016) {
                int a = sb[r_in * IMG_W + c];
#pragma unroll
                for (int o = 0; o < NOFF; o++) {
                    int c2 = c + DC[o];
                    if (c2 >= 0 && c2 < IMG_W) {       // rr <= 1022 < 1024 always
                        int d = a - (int)sb[(r_in + DR[o]) * IMG_W + c2];
                        acc[o] += (unsigned)(d * d);
                    }
                }
            }
        }
        // --- Bottom rows 1016..1023, full width (last tile only) ---
        if (r0 == 992) {
#pragma unroll 1
            for (int idx = tid; idx < 8 * IMG_W; idx += 256) {
                int r_in = 24 + (idx >> 10);           // 24..31 -> rows 1016..1023
                int c = idx & 1023;
                int gr = r0 + r_in;
                int a = sb[r_in * IMG_W + c];
#pragma unroll
                for (int o = 0; o < NOFF; o++) {
                    int rr = gr + DR[o];
                    int c2 = c + DC[o];
                    if (rr < IMG_H && c2 >= 0 && c2 < IMG_W) {
                        int d = a - (int)sb[(r_in + DR[o]) * IMG_W + c2];
                        acc[o] += (unsigned)(d * d);
                    }
                }
            }
        }
    }

    // --- Block reduce + global accumulate ---
#pragma unroll
    for (int o = 0; o < NOFF; o++)
        acc[o] = __reduce_add_sync(0xffffffffu, acc[o]);

    int warp = tid >> 5, lane = tid & 31;
    if (lane == 0) {
#pragma unroll
        for (int o = 0; o < NOFF; o++) part[warp][o] = acc[o];
    }
    __syncthreads();
    if (tid < NOFF) {
        unsigned long long s = 0;
#pragma unroll
        for (int w = 0; w < 8; w++) s += part[w][tid];
        atomicAdd(&g_sums[b * NOFF + tid], s);
    }
}

// ---------------------------------------------------------------------------
__global__ void k_final(float* __restrict__ out) {
    int t = blockIdx.x * blockDim.x + threadIdx.x;
    if (t >= NB * NOFF) return;
    const int DR[NOFF] = DR_TAB;
    const int DC[NOFF] = DC_TAB;
    int o = t & 15;
    int adc = DC[o] < 0 ? -DC[o] : DC[o];
    double cnt = (double)(IMG_H - DR[o]) * (double)(IMG_W - adc);
    out[t] = (float)((double)g_sums[t] / cnt);
}

extern "C" void kernel_launch(void* const* d_in, const int* in_sizes, int n_in,
                              void* d_out, int out_size) {
    const float* x = (const float*)d_in[0];
    float* out = (float*)d_out;

    k_minmax<<<dim3(NB, NPART), 256>>>(x);
    k_fused<<<dim3(IMG_H / TILE_R, NB), 256>>>(x);
    k_final<<<2, 256>>>(out);
}

// round 10
// speedup vs baseline: 3.3779x; 1.0694x over previous
#include <cuda_runtime.h>
#include <stdint.h>

#define NB 32
#define IMG_H 1024
#define IMG_W 1024
#define NPIX (IMG_H * IMG_W)
#define NOFF 16
#define NPART 32           // min/max partial blocks per image
#define TILE_R 32          // rows per fused block
#define SROWS (TILE_R + 7) // + halo rows for dr up to 7
#define NTILE (IMG_H / TILE_R)

// Scratch (static device globals — no dynamic allocation)
__device__ float               g_pmn[NB * NPART];
__device__ float               g_pmx[NB * NPART];
__device__ unsigned long long  g_sums[NB * NOFF];
__device__ unsigned int        g_done;

// Offset tables (order: for d in {1,3,5,7}, angle {0,45,90,135}: (dr, dc))
#define DR_TAB {0,1,1,1, 0,2,3,2, 0,4,5,4, 0,5,7,5}
#define DC_TAB {1,1,0,-1, 3,2,0,-2, 5,4,0,-4, 7,5,0,-5}

// ---------------------------------------------------------------------------
// Pass 1: per-image min/max partials (one partial per block, no atomics).
// Also zeroes g_sums / g_done.
// ---------------------------------------------------------------------------
__global__ void __launch_bounds__(256) k_minmax(const float* __restrict__ x) {
    int b = blockIdx.x, y = blockIdx.y;
    int tid = threadIdx.x;
    const float4* xb = (const float4*)(x + (size_t)b * NPIX);

    if (y == 0 && tid < NOFF) g_sums[b * NOFF + tid] = 0ull;
    if (b == 0 && y == 0 && tid == 0) g_done = 0u;

    float mn = 3.402823466e38f, mx = -3.402823466e38f;
    int idx = y * 256 + tid;
    int stride = NPART * 256;
#pragma unroll 8
    for (int i = idx; i < NPIX / 4; i += stride) {
        float4 v = xb[i];
        mn = fminf(mn, fminf(fminf(v.x, v.y), fminf(v.z, v.w)));
        mx = fmaxf(mx, fmaxf(fmaxf(v.x, v.y), fmaxf(v.z, v.w)));
    }
#pragma unroll
    for (int o = 16; o; o >>= 1) {
        mn = fminf(mn, __shfl_down_sync(0xffffffffu, mn, o));
        mx = fmaxf(mx, __shfl_down_sync(0xffffffffu, mx, o));
    }
    __shared__ float smn[8], smx[8];
    int warp = tid >> 5;
    if ((tid & 31) == 0) { smn[warp] = mn; smx[warp] = mx; }
    __syncthreads();
    if (tid == 0) {
        float a = smn[0], c = smx[0];
#pragma unroll
        for (int w = 1; w < 8; w++) { a = fminf(a, smn[w]); c = fmaxf(c, smx[w]); }
        g_pmn[b * NPART + y] = a;
        g_pmx[b * NPART + y] = c;
    }
}

// ---------------------------------------------------------------------------
// Pass 2: fused quantize (to smem) + SSD + final reduce (last block).
// Window W.u[12] covers tile bytes [c-16, c+32). Column (c+j) -> byte (16+j).
// ---------------------------------------------------------------------------
#define EXTW(sb) ( ((sb) & 3) ? __funnelshift_r(W.u[(sb) >> 2], W.u[((sb) >> 2) + 1], ((sb) & 3) * 8) \
                              : W.u[(sb) >> 2] )
#define ACCS(o, gg, dc, SS) { unsigned int _n = EXTW(16 + 4*(gg) + (dc)); \
                              unsigned int _d = __vabsdiffu4(SS[gg], _n); \
                              acc[o] = __dp4a(_d, _d, acc[o]); }
#define ACC4(o, dc, SS) { ACCS(o, 0, dc, SS) ACCS(o, 1, dc, SS) ACCS(o, 2, dc, SS) ACCS(o, 3, dc, SS) }

__global__ void __launch_bounds__(256) k_fused(const float* __restrict__ x,
                                               float* __restrict__ out) {
    __shared__ __align__(16) unsigned int sq[SROWS * 256];  // 39 KB quantized tile
    __shared__ unsigned int part[8][NOFF];
    __shared__ bool last;

    int b  = blockIdx.y;
    int r0 = blockIdx.x << 5;      // first source row of this tile
    int tid = threadIdx.x;

    // Reduce the min/max partials (uniform across block; broadcast loads)
    float mn = g_pmn[b * NPART], mx = g_pmx[b * NPART];
#pragma unroll
    for (int i = 1; i < NPART; i++) {
        mn = fminf(mn, g_pmn[b * NPART + i]);
        mx = fmaxf(mx, g_pmx[b * NPART + i]);
    }
    float scale = 255.0f / (mx - mn);
    float bias  = -mn * scale;

    // --- Quantize tile rows r0 .. r0+38 into smem (row k -> sq[k*256 ..]) ---
    const float4* xb = (const float4*)x + ((size_t)b << 18);  // 2^18 float4 / image
#pragma unroll
    for (int k = 0; k < SROWS; k++) {
        int gr = r0 + k;
        unsigned int w = 0;
        if (gr < IMG_H) {
            float4 v = xb[gr * 256 + tid];
            int q0 = min((int)fmaf(v.x, scale, bias), 255);
            int q1 = min((int)fmaf(v.y, scale, bias), 255);
            int q2 = min((int)fmaf(v.z, scale, bias), 255);
            int q3 = min((int)fmaf(v.w, scale, bias), 255);
            w = (unsigned)q0 | ((unsigned)q1 << 8) | ((unsigned)q2 << 16) | ((unsigned)q3 << 24);
        }
        sq[k * 256 + tid] = w;
    }
    __syncthreads();

    unsigned int acc[NOFF];
#pragma unroll
    for (int o = 0; o < NOFF; o++) acc[o] = 0;

    // --- Interior fast path: row-pairs share neighbor-row windows. ---
    // 16 row-pairs x 62 groups = 992 slots; each slot = 2 src rows x 16 px.
    for (int k = 0; k < 4; k++) {
        int slot = tid + (k << 8);
        int rp2 = slot / 62;           // row-pair index 0..15
        int g = (slot - rp2 * 62) + 1; // group 1..62
        int ri = rp2 * 2;              // first src row in tile (even)
        if (slot < 992 && (r0 + ri) < 1016) {
            const uint4* P4 = (const uint4*)(sq + ri * 256) + g;
            union { uint4 v[3]; unsigned int u[12]; } W;
            unsigned int S0[4], S1[4];

            // k=0 : src0 dr0 (dc 1,3,5,7)
            W.v[1] = P4[0];  W.v[2] = P4[1];
            S0[0] = W.u[4]; S0[1] = W.u[5]; S0[2] = W.u[6]; S0[3] = W.u[7];
            ACC4(0, 1, S0)  ACC4(4, 3, S0)  ACC4(8, 5, S0)  ACC4(12, 7, S0)
            { // k=1 : src0 dr1 (-1,0,1) + src1 dr0 (1,3,5,7)
                const uint4* rp = P4 + 64;
                W.v[0] = rp[-1]; W.v[1] = rp[0]; W.v[2] = rp[1];
                S1[0] = W.u[4]; S1[1] = W.u[5]; S1[2] = W.u[6]; S1[3] = W.u[7];
                ACC4(1, 1, S0)  ACC4(2, 0, S0)  ACC4(3, -1, S0)
                ACC4(0, 1, S1)  ACC4(4, 3, S1)  ACC4(8, 5, S1)  ACC4(12, 7, S1)
            }
            { // k=2 : src0 dr2 (±2) + src1 dr1 (-1,0,1)
                const uint4* rp = P4 + 128;
                W.v[0] = rp[-1]; W.v[1] = rp[0]; W.v[2] = rp[1];
                ACC4(5, 2, S0)  ACC4(7, -2, S0)
                ACC4(1, 1, S1)  ACC4(2, 0, S1)  ACC4(3, -1, S1)
            }
            { // k=3 : src0 dr3 (0) + src1 dr2 (±2)
                const uint4* rp = P4 + 192;
                W.v[0] = rp[-1]; W.v[1] = rp[0]; W.v[2] = rp[1];
                ACC4(6, 0, S0)
                ACC4(5, 2, S1)  ACC4(7, -2, S1)
            }
            { // k=4 : src0 dr4 (±4) + src1 dr3 (0)
                const uint4* rp = P4 + 256;
                W.v[0] = rp[-1]; W.v[1] = rp[0]; W.v[2] = rp[1];
                ACC4(9, 4, S0)  ACC4(11, -4, S0)
                ACC4(6, 0, S1)
            }
            { // k=5 : src0 dr5 (-5,0,5) + src1 dr4 (±4)
                const uint4* rp = P4 + 320;
                W.v[0] = rp[-1]; W.v[1] = rp[0]; W.v[2] = rp[1];
                ACC4(10, 0, S0) ACC4(13, 5, S0) ACC4(15, -5, S0)
                ACC4(9, 4, S1)  ACC4(11, -4, S1)
            }
            { // k=6 : src1 dr5 (-5,0,5)
                const uint4* rp = P4 + 384;
                W.v[0] = rp[-1]; W.v[1] = rp[0]; W.v[2] = rp[1];
                ACC4(10, 0, S1) ACC4(13, 5, S1) ACC4(15, -5, S1)
            }
            { // k=7 : src0 dr7 (0)
                const uint4* rp = P4 + 448;
                W.v[1] = rp[0];
                ACC4(14, 0, S0)
            }
            { // k=8 : src1 dr7 (0)
                const uint4* rp = P4 + 512;
                W.v[1] = rp[0];
                ACC4(14, 0, S1)
            }
        }
    }

    // --- Side-column borders of this tile (c<16 or c>=1008), rows < 1016 ---
    {
        const uint8_t* sb = (const uint8_t*)sq;
        const int DR[NOFF] = DR_TAB;
        const int DC[NOFF] = DC_TAB;
#pragma unroll 1
        for (int idx = tid; idx < TILE_R * 32; idx += 256) {
            int r_in = idx >> 5;
            int cc = idx & 31;
            int c = (cc < 16) ? cc : cc + 992;
            if ((r0 + r_in) < 1016) {
                int a = sb[r_in * IMG_W + c];
#pragma unroll
                for (int o = 0; o < NOFF; o++) {
                    int c2 = c + DC[o];
                    if (c2 >= 0 && c2 < IMG_W) {       // rr <= 1022 < 1024 always
                        int d = a - (int)sb[(r_in + DR[o]) * IMG_W + c2];
                        acc[o] += (unsigned)(d * d);
                    }
                }
            }
        }
        // --- Bottom rows 1016..1023, full width (last tile only) ---
        if (r0 == 992) {
#pragma unroll 1
            for (int idx = tid; idx < 8 * IMG_W; idx += 256) {
                int r_in = 24 + (idx >> 10);           // rows 1016..1023
                int c = idx & 1023;
                int gr = r0 + r_in;
                int a = sb[r_in * IMG_W + c];
#pragma unroll
                for (int o = 0; o < NOFF; o++) {
                    int rr = gr + DR[o];
                    int c2 = c + DC[o];
                    if (rr < IMG_H && c2 >= 0 && c2 < IMG_W) {
                        int d = a - (int)sb[(r_in + DR[o]) * IMG_W + c2];
                        acc[o] += (unsigned)(d * d);
                    }
                }
            }
        }
    }

    // --- Block reduce + global accumulate ---
#pragma unroll
    for (int o = 0; o < NOFF; o++)
        acc[o] = __reduce_add_sync(0xffffffffu, acc[o]);

    int warp = tid >> 5, lane = tid & 31;
    if (lane == 0) {
#pragma unroll
        for (int o = 0; o < NOFF; o++) part[warp][o] = acc[o];
    }
    __syncthreads();
    if (tid < NOFF) {
        unsigned long long s = 0;
#pragma unroll
        for (int w = 0; w < 8; w++) s += part[w][tid];
        atomicAdd(&g_sums[b * NOFF + tid], s);
    }

    // --- Last block finalizes the output (replaces k_final launch) ---
    __syncthreads();
    if (tid == 0) {
        __threadfence();
        unsigned int old = atomicAdd(&g_done, 1u);
        last = (old == (unsigned)(NTILE * NB - 1));
    }
    __syncthreads();
    if (last) {
        const int DR[NOFF] = DR_TAB;
        const int DC[NOFF] = DC_TAB;
        for (int t = tid; t < NB * NOFF; t += 256) {
            unsigned long long sv = atomicAdd(&g_sums[t], 0ull);  // L2-coherent read
            int o = t & 15;
            int adc = DC[o] < 0 ? -DC[o] : DC[o];
            double cnt = (double)(IMG_H - DR[o]) * (double)(IMG_W - adc);
            out[t] = (float)((double)sv / cnt);
        }
    }
}

extern "C" void kernel_launch(void* const* d_in, const int* in_sizes, int n_in,
                              void* d_out, int out_size) {
    const float* x = (const float*)d_in[0];
    float* out = (float*)d_out;

    k_minmax<<<dim3(NB, NPART), 256>>>(x);
    k_fused<<<dim3(NTILE, NB), 256>>>(x, out);
}